// round 17
// baseline (speedup 1.0000x reference)
#include <cuda_runtime.h>
#include <cuda_fp16.h>
#include <math.h>
#include <stdint.h>

#define N_TOK  2048
#define DIMM   1024
#define NBATCH 2
#define NHEAD  16
#define DHEAD  64
#define NQT    (N_TOK / 128)
#define BETA_LOG2E 0.1803368801111244f   /* 0.125 * log2(e) */

// Scratch (static device allocations — no cudaMalloc anywhere)
__device__ __half g_qkh[(size_t)(NBATCH * N_TOK) * (2 * DIMM)];
__device__ __half g_aoh[(size_t)(NBATCH * N_TOK) * DIMM];
__device__ __half g_xh[(size_t)(NBATCH * N_TOK) * DIMM];
__device__ __half g_wqkh[(size_t)DIMM * (2 * DIMM)];
__device__ __half g_woh[(size_t)DIMM * DIMM];

// ---------------------------------------------------------------------------
// helpers
// ---------------------------------------------------------------------------
__device__ __forceinline__ void mma_f16(
    float& c0, float& c1, float& c2, float& c3,
    unsigned a0, unsigned a1, unsigned a2, unsigned a3,
    unsigned b0, unsigned b1)
{
    asm volatile(
        "mma.sync.aligned.m16n8k16.row.col.f32.f16.f16.f32 "
        "{%0,%1,%2,%3}, {%4,%5,%6,%7}, {%8,%9}, {%0,%1,%2,%3};"
        : "+f"(c0), "+f"(c1), "+f"(c2), "+f"(c3)
        : "r"(a0), "r"(a1), "r"(a2), "r"(a3), "r"(b0), "r"(b1));
}

__device__ __forceinline__ void cp_async16(void* smem, const void* gmem) {
    unsigned saddr = (unsigned)__cvta_generic_to_shared(smem);
    asm volatile("cp.async.cg.shared.global [%0], [%1], 16;"
                 :: "r"(saddr), "l"(gmem));
}

__device__ __forceinline__ void ldsm_x4(
    unsigned& r0, unsigned& r1, unsigned& r2, unsigned& r3, const void* p)
{
    unsigned a = (unsigned)__cvta_generic_to_shared(p);
    asm volatile("ldmatrix.sync.aligned.m8n8.x4.shared.b16 {%0,%1,%2,%3}, [%4];"
                 : "=r"(r0), "=r"(r1), "=r"(r2), "=r"(r3) : "r"(a));
}

__device__ __forceinline__ void ldsm_x4t(
    unsigned& r0, unsigned& r1, unsigned& r2, unsigned& r3, const void* p)
{
    unsigned a = (unsigned)__cvta_generic_to_shared(p);
    asm volatile("ldmatrix.sync.aligned.m8n8.x4.trans.shared.b16 {%0,%1,%2,%3}, [%4];"
                 : "=r"(r0), "=r"(r1), "=r"(r2), "=r"(r3) : "r"(a));
}

__device__ __forceinline__ unsigned h2u(__half2 v) {
    return *reinterpret_cast<unsigned*>(&v);
}

// ---------------------------------------------------------------------------
// Fused fp32 -> fp16 convert of x, W_qk, W_out (one launch, 2 float4/thread)
// ---------------------------------------------------------------------------
__global__ void __launch_bounds__(256) conv3_kernel(
    const float* __restrict__ s0, __half* __restrict__ d0, int n0,
    const float* __restrict__ s1, __half* __restrict__ d1, int n1,
    const float* __restrict__ s2, __half* __restrict__ d2, int n2)
{
    int base = blockIdx.x * 512 + threadIdx.x;
#pragma unroll
    for (int u = 0; u < 2; u++) {
        int i = base + u * 256;
        const float* s; __half* d; int j = i;
        if (j < n0)                { s = s0; d = d0; }
        else if ((j -= n0) < n1)   { s = s1; d = d1; }
        else if ((j -= n1) < n2)   { s = s2; d = d2; }
        else continue;
        float4 v = ((const float4*)s)[j];
        ((__half2*)d)[2 * j]     = __floats2half2_rn(v.x, v.y);
        ((__half2*)d)[2 * j + 1] = __floats2half2_rn(v.z, v.w);
    }
}

// ---------------------------------------------------------------------------
// fp16 GEMM: 128x128 tile, BK=32, 3-stage cp.async, ONE barrier per iter
// (stage ring mod 3 makes the trailing barrier redundant), loads hoisted
// ahead of the mma loop.
// ---------------------------------------------------------------------------
#define AS_STRH 40
#define BS_STRH 136

template <bool OUT_HALF>
__global__ void __launch_bounds__(256) hgemm_kernel(
    const __half* __restrict__ A, const __half* __restrict__ B,
    void* __restrict__ Cv, int M, int N, int K)
{
    __shared__ __half As[3][128][AS_STRH];
    __shared__ __half Bs[3][32][BS_STRH];

    const int tid  = threadIdx.x;
    const int w    = tid >> 5;
    const int lane = tid & 31;
    const int g    = lane >> 2;
    const int t    = lane & 3;
    const int wm   = (w & 3) * 32;
    const int wn   = (w >> 2) * 64;

    const int mbase = blockIdx.y * 128;
    const int nbase = blockIdx.x * 128;

    const int ar0 = tid >> 2,         ac0 = (tid & 3) * 8;
    const int ar1 = (tid + 256) >> 2, ac1 = ((tid + 256) & 3) * 8;
    const int br0 = tid >> 4,         bc0 = (tid & 15) * 8;
    const int br1 = (tid + 256) >> 4, bc1 = ((tid + 256) & 15) * 8;

    const int lrow = (lane & 7) + ((lane >> 3) & 1) * 8;
    const int lcol = (lane >> 4) * 8;
    const int tkrow = (lane & 7) + ((lane >> 3) & 1) * 8;
    const int tncol = (lane >> 4) * 8;

    float acc[2][8][4];
#pragma unroll
    for (int mt = 0; mt < 2; mt++)
#pragma unroll
        for (int nt = 0; nt < 8; nt++)
#pragma unroll
            for (int j = 0; j < 4; j++) acc[mt][nt][j] = 0.f;

    const int NIT = K / 32;

#define GLOAD(S, K0)                                                           \
    {                                                                          \
        cp_async16(&As[S][ar0][ac0], A + (size_t)(mbase + ar0) * K + (K0) + ac0); \
        cp_async16(&As[S][ar1][ac1], A + (size_t)(mbase + ar1) * K + (K0) + ac1); \
        cp_async16(&Bs[S][br0][bc0], B + (size_t)((K0) + br0) * N + nbase + bc0); \
        cp_async16(&Bs[S][br1][bc1], B + (size_t)((K0) + br1) * N + nbase + bc1); \
        asm volatile("cp.async.commit_group;");                                \
    }

    GLOAD(0, 0);
    GLOAD(1, 32);

    for (int it = 0; it < NIT; it++) {
        const int buf = it % 3;
        if (it + 1 < NIT)
            asm volatile("cp.async.wait_group 1;");
        else
            asm volatile("cp.async.wait_group 0;");
        __syncthreads();   // single barrier per iter

        unsigned af[2][2][4];
#pragma unroll
        for (int kch = 0; kch < 2; kch++)
#pragma unroll
            for (int mt = 0; mt < 2; mt++)
                ldsm_x4(af[kch][mt][0], af[kch][mt][1], af[kch][mt][2], af[kch][mt][3],
                        &As[buf][wm + mt * 16 + lrow][kch * 16 + lcol]);

        if (it + 2 < NIT) {
            GLOAD((it + 2) % 3, (it + 2) * 32);
        }

#pragma unroll
        for (int kch = 0; kch < 2; kch++) {
#pragma unroll
            for (int ntp = 0; ntp < 4; ntp++) {
                unsigned b[4];
                ldsm_x4t(b[0], b[1], b[2], b[3],
                         &Bs[buf][kch * 16 + tkrow][wn + ntp * 16 + tncol]);
#pragma unroll
                for (int mt = 0; mt < 2; mt++) {
                    mma_f16(acc[mt][2 * ntp][0], acc[mt][2 * ntp][1],
                            acc[mt][2 * ntp][2], acc[mt][2 * ntp][3],
                            af[kch][mt][0], af[kch][mt][1], af[kch][mt][2], af[kch][mt][3],
                            b[0], b[1]);
                    mma_f16(acc[mt][2 * ntp + 1][0], acc[mt][2 * ntp + 1][1],
                            acc[mt][2 * ntp + 1][2], acc[mt][2 * ntp + 1][3],
                            af[kch][mt][0], af[kch][mt][1], af[kch][mt][2], af[kch][mt][3],
                            b[2], b[3]);
                }
            }
        }
    }
#undef GLOAD

#pragma unroll
    for (int mt = 0; mt < 2; mt++) {
        const int r0 = mbase + wm + mt * 16 + g;
#pragma unroll
        for (int nt = 0; nt < 8; nt++) {
            const int col = nbase + wn + nt * 8 + 2 * t;
            if (OUT_HALF) {
                __half* Ch = (__half*)Cv;
                *(__half2*)(Ch + (size_t)r0 * N + col) =
                    __floats2half2_rn(acc[mt][nt][0], acc[mt][nt][1]);
                *(__half2*)(Ch + (size_t)(r0 + 8) * N + col) =
                    __floats2half2_rn(acc[mt][nt][2], acc[mt][nt][3]);
            } else {
                float* Cf = (float*)Cv;
                *(float2*)(Cf + (size_t)r0 * N + col) =
                    make_float2(acc[mt][nt][0], acc[mt][nt][1]);
                *(float2*)(Cf + (size_t)(r0 + 8) * N + col) =
                    make_float2(acc[mt][nt][2], acc[mt][nt][3]);
            }
        }
    }
}

// ---------------------------------------------------------------------------
// fp16 causal flash attention v5: 128-key stages in a 3-stage ring, ONE
// barrier per pair, fill hoisted ahead of compute. K tile serves S (ldmatrix)
// and PV (ldmatrix.trans). Base-2 softmax; P stays in registers.
// ---------------------------------------------------------------------------
#define KS_STRH 72
#define KS_HALVES (3 * 128 * KS_STRH)
#define ATTN_SMEM_BYTES (KS_HALVES * 2)   // 55296 B

__global__ void __launch_bounds__(256, 2) attn_tc_kernel(
    const __half* __restrict__ qk, __half* __restrict__ out)
{
    extern __shared__ __half smh[];
    __half* Ks = smh;

    const int bx = blockIdx.x, h = blockIdx.y, bb = blockIdx.z;
    const int tid  = threadIdx.x;
    const int w    = tid >> 5;
    const int lane = tid & 31;
    const int g    = lane >> 2;
    const int t    = lane & 3;

    const int srow  = lane & 7;
    const int scol  = (lane >> 3) * 8;
    const int tkrow = (lane & 7) + ((lane >> 3) & 1) * 8;
    const int tncol = (lane >> 4) * 8;

    const __half2 scale2 = __float2half2_rn(BETA_LOG2E);

    const __half* kbase = qk + (size_t)bb * N_TOK * (2 * DIMM) + DIMM + h * DHEAD;

#define FILL_KP(P, BUF)                                                        \
    {                                                                          \
        _Pragma("unroll")                                                      \
        for (int i = tid; i < 128 * 8; i += 256) {                             \
            int r = i >> 3, c = (i & 7) * 8;                                   \
            cp_async16(&Ks[((BUF) * 128 + r) * KS_STRH + c],                   \
                       kbase + (size_t)((P) * 128 + r) * (2 * DIMM) + c);      \
        }                                                                      \
        asm volatile("cp.async.commit_group;");                                \
    }

    for (int phase = 0; phase < 2; phase++) {
        const int qt = (phase == 0) ? bx : (NQT - 1 - bx);

        const int qrow0 = bb * N_TOK + qt * 128 + w * 16;
        unsigned qf[4][4];
        {
            const __half* qp  = qk + (size_t)(qrow0 + g) * (2 * DIMM) + h * DHEAD;
            const __half* qp8 = qp + (size_t)8 * (2 * DIMM);
#pragma unroll
            for (int kc = 0; kc < 4; kc++) {
                __half2 a0 = *(const __half2*)(qp  + kc * 16 + 2 * t);
                __half2 a1 = *(const __half2*)(qp8 + kc * 16 + 2 * t);
                __half2 a2 = *(const __half2*)(qp  + kc * 16 + 8 + 2 * t);
                __half2 a3 = *(const __half2*)(qp8 + kc * 16 + 8 + 2 * t);
                qf[kc][0] = h2u(__hmul2(a0, scale2));
                qf[kc][1] = h2u(__hmul2(a1, scale2));
                qf[kc][2] = h2u(__hmul2(a2, scale2));
                qf[kc][3] = h2u(__hmul2(a3, scale2));
            }
        }

        float o[8][4];
#pragma unroll
        for (int nt = 0; nt < 8; nt++)
#pragma unroll
            for (int j = 0; j < 4; j++) o[nt][j] = 0.f;
        float m0 = -1e30f, m1 = -1e30f, l0 = 0.f, l1 = 0.f;

        const int diagw = 2 * qt + (w >> 2);
        const int npair = qt + 1;

        FILL_KP(0, 0);
        if (npair > 1) FILL_KP(1, 1);

        for (int p = 0; p < npair; p++) {
            const int st = p % 3;
            if (p + 1 < npair)
                asm volatile("cp.async.wait_group 1;");
            else
                asm volatile("cp.async.wait_group 0;");
            __syncthreads();   // single barrier per pair

            if (p + 2 < npair) FILL_KP(p + 2, (p + 2) % 3);

#pragma unroll
            for (int sub = 0; sub < 2; sub++) {
                const int kt = 2 * p + sub;
                if (kt > diagw) continue;
                const __half* KsB = Ks + ((size_t)st * 128 + sub * 64) * KS_STRH;

                // ---- S = Q @ K^T (base-2-scaled) ----
                float sc[8][4];
#pragma unroll
                for (int nt = 0; nt < 8; nt++) {
                    sc[nt][0] = sc[nt][1] = sc[nt][2] = sc[nt][3] = 0.f;
                    const __half* kr = KsB + (nt * 8 + srow) * KS_STRH + scol;
                    unsigned b[4];
                    ldsm_x4(b[0], b[1], b[2], b[3], kr);
                    mma_f16(sc[nt][0], sc[nt][1], sc[nt][2], sc[nt][3],
                            qf[0][0], qf[0][1], qf[0][2], qf[0][3], b[0], b[1]);
                    mma_f16(sc[nt][0], sc[nt][1], sc[nt][2], sc[nt][3],
                            qf[1][0], qf[1][1], qf[1][2], qf[1][3], b[2], b[3]);
                    ldsm_x4(b[0], b[1], b[2], b[3], kr + 32);
                    mma_f16(sc[nt][0], sc[nt][1], sc[nt][2], sc[nt][3],
                            qf[2][0], qf[2][1], qf[2][2], qf[2][3], b[0], b[1]);
                    mma_f16(sc[nt][0], sc[nt][1], sc[nt][2], sc[nt][3],
                            qf[3][0], qf[3][1], qf[3][2], qf[3][3], b[2], b[3]);
                }

                // ---- causal mask (warp's diagonal tile only) ----
                if (kt == diagw) {
                    const int lr0 = w * 16 + g, lr1 = lr0 + 8;
                    const int cb  = (w >> 2) * 64;
#pragma unroll
                    for (int nt = 0; nt < 8; nt++) {
                        int col = cb + nt * 8 + 2 * t;
                        if (col     > lr0) sc[nt][0] = -1e30f;
                        if (col + 1 > lr0) sc[nt][1] = -1e30f;
                        if (col     > lr1) sc[nt][2] = -1e30f;
                        if (col + 1 > lr1) sc[nt][3] = -1e30f;
                    }
                }

                // ---- online softmax (base-2) ----
                float tmax0 = -1e30f, tmax1 = -1e30f;
#pragma unroll
                for (int nt = 0; nt < 8; nt++) {
                    tmax0 = fmaxf(tmax0, fmaxf(sc[nt][0], sc[nt][1]));
                    tmax1 = fmaxf(tmax1, fmaxf(sc[nt][2], sc[nt][3]));
                }
                tmax0 = fmaxf(tmax0, __shfl_xor_sync(0xffffffffu, tmax0, 1));
                tmax0 = fmaxf(tmax0, __shfl_xor_sync(0xffffffffu, tmax0, 2));
                tmax1 = fmaxf(tmax1, __shfl_xor_sync(0xffffffffu, tmax1, 1));
                tmax1 = fmaxf(tmax1, __shfl_xor_sync(0xffffffffu, tmax1, 2));

                float mn0 = fmaxf(m0, tmax0), mn1 = fmaxf(m1, tmax1);
                float corr0 = exp2f(m0 - mn0), corr1 = exp2f(m1 - mn1);
                m0 = mn0; m1 = mn1;

                unsigned pu0[8], pu1[8];
                float ls0 = 0.f, ls1 = 0.f;
#pragma unroll
                for (int nt = 0; nt < 8; nt++) {
                    __half2 p01 = h2exp2(
                        __floats2half2_rn(sc[nt][0] - mn0, sc[nt][1] - mn0));
                    __half2 p23 = h2exp2(
                        __floats2half2_rn(sc[nt][2] - mn1, sc[nt][3] - mn1));
                    pu0[nt] = h2u(p01);
                    pu1[nt] = h2u(p23);
                    float2 f0 = __half22float2(p01);
                    float2 f1 = __half22float2(p23);
                    ls0 += f0.x + f0.y;
                    ls1 += f1.x + f1.y;
                }
                ls0 += __shfl_xor_sync(0xffffffffu, ls0, 1);
                ls0 += __shfl_xor_sync(0xffffffffu, ls0, 2);
                ls1 += __shfl_xor_sync(0xffffffffu, ls1, 1);
                ls1 += __shfl_xor_sync(0xffffffffu, ls1, 2);
                l0 = l0 * corr0 + ls0;
                l1 = l1 * corr1 + ls1;

#pragma unroll
                for (int nt = 0; nt < 8; nt++) {
                    o[nt][0] *= corr0; o[nt][1] *= corr0;
                    o[nt][2] *= corr1; o[nt][3] *= corr1;
                }

                // ---- O += P @ V (B-frags via ldmatrix.trans on K tile) ----
#pragma unroll
                for (int kc = 0; kc < 4; kc++) {
                    const unsigned a0 = pu0[2 * kc],     a1 = pu1[2 * kc];
                    const unsigned a2 = pu0[2 * kc + 1], a3 = pu1[2 * kc + 1];
                    const __half* vr = KsB + (kc * 16 + tkrow) * KS_STRH + tncol;
#pragma unroll
                    for (int ntp = 0; ntp < 4; ntp++) {
                        unsigned b[4];
                        ldsm_x4t(b[0], b[1], b[2], b[3], vr + ntp * 16);
                        mma_f16(o[2 * ntp][0], o[2 * ntp][1],
                                o[2 * ntp][2], o[2 * ntp][3],
                                a0, a1, a2, a3, b[0], b[1]);
                        mma_f16(o[2 * ntp + 1][0], o[2 * ntp + 1][1],
                                o[2 * ntp + 1][2], o[2 * ntp + 1][3],
                                a0, a1, a2, a3, b[2], b[3]);
                    }
                }
            }
        }

        // ---- epilogue: normalize, convert to fp16 (feeds GEMM2) ----
        const float inv0 = 1.f / l0, inv1 = 1.f / l1;
        __half* op0 = out + (size_t)(qrow0 + g) * DIMM + h * DHEAD;
        __half* op1 = op0 + (size_t)8 * DIMM;
#pragma unroll
        for (int nt = 0; nt < 8; nt++) {
            *(__half2*)(op0 + nt * 8 + 2 * t) =
                __floats2half2_rn(o[nt][0] * inv0, o[nt][1] * inv0);
            *(__half2*)(op1 + nt * 8 + 2 * t) =
                __floats2half2_rn(o[nt][2] * inv1, o[nt][3] * inv1);
        }
        __syncthreads();   // all warps done with Ks before next phase refills
    }
#undef FILL_KP
}

// ---------------------------------------------------------------------------
extern "C" void kernel_launch(void* const* d_in, const int* in_sizes, int n_in,
                              void* d_out, int out_size)
{
    const float* x     = (const float*)d_in[0];
    const float* W_qk  = (const float*)d_in[1];
    const float* W_out = (const float*)d_in[2];
    float* out = (float*)d_out;

    __half *qkh, *aoh, *xh, *wqkh, *woh;
    cudaGetSymbolAddress((void**)&qkh,  g_qkh);
    cudaGetSymbolAddress((void**)&aoh,  g_aoh);
    cudaGetSymbolAddress((void**)&xh,   g_xh);
    cudaGetSymbolAddress((void**)&wqkh, g_wqkh);
    cudaGetSymbolAddress((void**)&woh,  g_woh);

    static bool attr_set = false;
    if (!attr_set) {
        cudaFuncSetAttribute(attn_tc_kernel,
                             cudaFuncAttributeMaxDynamicSharedMemorySize,
                             ATTN_SMEM_BYTES);
        attr_set = true;
    }

    const int nx  = NBATCH * N_TOK * DIMM / 4;
    const int nwq = DIMM * 2 * DIMM / 4;
    const int nwo = DIMM * DIMM / 4;
    const int ntot = nx + nwq + nwo;
    conv3_kernel<<<(ntot + 511) / 512, 256>>>(x, xh, nx, W_qk, wqkh, nwq,
                                              W_out, woh, nwo);

    // qk = x @ W_qk  (fp16 in/out, fp32 accum)
    hgemm_kernel<true><<<dim3((2 * DIMM) / 128, (NBATCH * N_TOK) / 128), 256>>>(
        xh, wqkh, qkh, NBATCH * N_TOK, 2 * DIMM, DIMM);
    // causal attention (fp16, base-2 softmax, register P, 3-stage 128-key ring)
    attn_tc_kernel<<<dim3(NQT / 2, NHEAD, NBATCH), 256, ATTN_SMEM_BYTES>>>(
        qkh, aoh);
    // out = ao @ W_out  (fp16 in, fp32 out)
    hgemm_kernel<false><<<dim3(DIMM / 128, (NBATCH * N_TOK) / 128), 256>>>(
        aoh, woh, out, NBATCH * N_TOK, DIMM, DIMM);
}